// round 5
// baseline (speedup 1.0000x reference)
#include <cuda_runtime.h>

#define SEQL 601
#define BATCH 512
#define ZS 100
#define FLATD 5
#define HID 256
#define IN1 105  // ZS + FLATD

// ---------------- scratch (__device__ globals; no allocation) ----------------
// Repacked weights: [k][u][gate], gate order i,f,g,o  (float4 per (k,u))
__device__ float g_w1i[HID * HID * 4];
__device__ float g_w1h[HID * HID * 4];
__device__ float g_w2i[HID * HID * 4];
__device__ float g_w2h[HID * HID * 4];
__device__ float g_b1[HID * 4];      // [u][gate] = b_ih + b_hh
__device__ float g_b2[HID * 4];
__device__ float g_fc1t[IN1 * HID];  // [k][n]  (transposed fc1_w)

// ---------------- weight repack kernel (cheap, runs every launch) ------------
__global__ void repack_kernel(const float* __restrict__ w_ih1,
                              const float* __restrict__ w_hh1,
                              const float* __restrict__ w_ih2,
                              const float* __restrict__ w_hh2,
                              const float* __restrict__ b_ih1,
                              const float* __restrict__ b_hh1,
                              const float* __restrict__ b_ih2,
                              const float* __restrict__ b_hh2,
                              const float* __restrict__ fc1_w) {
    int idx = blockIdx.x * blockDim.x + threadIdx.x;
    const int NW = HID * HID * 4;  // 262144 per matrix
    if (idx < 4 * NW) {
        int m = idx / NW;
        int e = idx % NW;
        int g = e & 3;
        int u = (e >> 2) & (HID - 1);
        int k = e >> 10;
        const float* src = (m == 0) ? w_ih1 : (m == 1) ? w_hh1 : (m == 2) ? w_ih2 : w_hh2;
        float v = src[(g * HID + u) * HID + k];
        float* dst = (m == 0) ? g_w1i : (m == 1) ? g_w1h : (m == 2) ? g_w2i : g_w2h;
        dst[e] = v;
    } else {
        int e = idx - 4 * NW;
        if (e < 2 * HID * 4) {  // 2048 bias entries
            int which = e / (HID * 4);
            int r = e % (HID * 4);
            int g = r & 3, u = r >> 2;
            if (which == 0)
                g_b1[r] = b_ih1[g * HID + u] + b_hh1[g * HID + u];
            else
                g_b2[r] = b_ih2[g * HID + u] + b_hh2[g * HID + u];
        } else {
            e -= 2 * HID * 4;
            if (e < IN1 * HID) {
                int n = e % HID, k = e / HID;
                g_fc1t[k * HID + n] = fc1_w[n * IN1 + k];
            }
        }
    }
}

// ---------------- activations (exact saturation at +-inf) --------------------
__device__ __forceinline__ float sigm_f(float x) {
    // 1/(1+e^-x); e^-x -> inf gives 0, e^-x -> 0 gives 1.  err ~1e-6
    return __fdividef(1.0f, 1.0f + __expf(-x));
}
__device__ __forceinline__ float tanh_f(float x) {
    // 2/(1+e^-2x) - 1 ; e -> inf gives -1, e -> 0 gives +1 (no NaN at saturation)
    float e = __expf(-2.0f * x);
    return __fdividef(2.0f, 1.0f + e) - 1.0f;
}

// ---------------- LSTM cell stage: thread u owns hidden unit u ---------------
// wi/wh: [k][u] float4 (4 gates). xin/hin read (broadcast), hout[r][u] written.
__device__ __forceinline__ void lstm_stage(const float4* __restrict__ wi,
                                           const float4* __restrict__ wh,
                                           float4 bv,
                                           float (*xin)[HID],
                                           float (*hin)[HID],
                                           float (*hout)[HID],
                                           float* c, int u) {
    float acc0[4], acc1[4], acc2[4], acc3[4];
#pragma unroll
    for (int r = 0; r < 4; r++) {
        acc0[r] = bv.x; acc1[r] = bv.y; acc2[r] = bv.z; acc3[r] = bv.w;
    }
#pragma unroll 2
    for (int k4 = 0; k4 < HID / 4; k4++) {
        float xs[4][4], hs[4][4];
#pragma unroll
        for (int r = 0; r < 4; r++) {
            *(float4*)xs[r] = *(const float4*)&xin[r][k4 * 4];
            *(float4*)hs[r] = *(const float4*)&hin[r][k4 * 4];
        }
#pragma unroll
        for (int kk = 0; kk < 4; kk++) {
            float4 a = wi[(k4 * 4 + kk) * HID + u];
            float4 b = wh[(k4 * 4 + kk) * HID + u];
#pragma unroll
            for (int r = 0; r < 4; r++) {
                float xv = xs[r][kk];
                float hv = hs[r][kk];
                acc0[r] += a.x * xv; acc1[r] += a.y * xv;
                acc2[r] += a.z * xv; acc3[r] += a.w * xv;
                acc0[r] += b.x * hv; acc1[r] += b.y * hv;
                acc2[r] += b.z * hv; acc3[r] += b.w * hv;
            }
        }
    }
#pragma unroll
    for (int r = 0; r < 4; r++) {
        float iv = sigm_f(acc0[r]);
        float fv = sigm_f(acc1[r]);
        float gv = tanh_f(acc2[r]);
        float ov = sigm_f(acc3[r]);
        float cn = fv * c[r] + iv * gv;
        c[r] = cn;
        hout[r][u] = ov * tanh_f(cn);
    }
}

// ---------------- main persistent kernel: CTA owns 4 batch rows --------------
__global__ void __launch_bounds__(256, 1) gen_kernel(
    const float* __restrict__ z,         // [B][S][ZS]
    const float* __restrict__ prev_gen,  // [B][FLATD]
    const float* __restrict__ fc1_b,     // [HID]
    const float* __restrict__ fc2_w,     // [FLATD][HID]
    const float* __restrict__ fc2_b,     // [FLATD]
    float* __restrict__ out)             // [B][S][FLATD]
{
    __shared__ __align__(16) float insm[4][112];       // [row][k<105]; [100..104] = prev
    __shared__ __align__(16) float xsm[4][HID];
    __shared__ __align__(16) float h1sm[2][4][HID];
    __shared__ __align__(16) float h2sm[2][4][HID];

    const int u = threadIdx.x;
    const int b0 = blockIdx.x * 4;

    // init state
#pragma unroll
    for (int r = 0; r < 4; r++) {
        h1sm[0][r][u] = 0.0f;
        h2sm[0][r][u] = 0.0f;
    }
    if (u < 20) {
        int r = u / 5, j = u % 5;
        insm[r][ZS + j] = prev_gen[(b0 + r) * FLATD + j];
    }
    float c1[4] = {0.f, 0.f, 0.f, 0.f};
    float c2[4] = {0.f, 0.f, 0.f, 0.f};
    const float fb = fc1_b[u];
    const float4 b1v = ((const float4*)g_b1)[u];
    const float4 b2v = ((const float4*)g_b2)[u];
    const float4* w1i = (const float4*)g_w1i;
    const float4* w1h = (const float4*)g_w1h;
    const float4* w2i = (const float4*)g_w2i;
    const float4* w2h = (const float4*)g_w2h;
    __syncthreads();

    int cur = 0;
    for (int t = 0; t < SEQL; ++t) {
        // ---- stage 1: stage z rows into smem ----
        for (int e = u; e < 4 * ZS; e += 256) {
            int r = e / ZS, k = e % ZS;
            insm[r][k] = z[(size_t)(b0 + r) * (SEQL * ZS) + (size_t)t * ZS + k];
        }
        __syncthreads();

        // ---- stage 2: fc1 + relu -> x ----
        {
            float a0 = fb, a1 = fb, a2 = fb, a3 = fb;
#pragma unroll 5
            for (int k = 0; k < IN1; k++) {
                float w = g_fc1t[k * HID + u];
                a0 += w * insm[0][k];
                a1 += w * insm[1][k];
                a2 += w * insm[2][k];
                a3 += w * insm[3][k];
            }
            xsm[0][u] = fmaxf(a0, 0.0f);
            xsm[1][u] = fmaxf(a1, 0.0f);
            xsm[2][u] = fmaxf(a2, 0.0f);
            xsm[3][u] = fmaxf(a3, 0.0f);
        }
        __syncthreads();

        // ---- stage 3: LSTM1 (reads xsm, h1[cur]; writes h1[1-cur]) ----
        lstm_stage(w1i, w1h, b1v, xsm, h1sm[cur], h1sm[1 - cur], c1, u);
        __syncthreads();

        // ---- stage 4: LSTM2 (reads h1[1-cur], h2[cur]; writes h2[1-cur]) ----
        lstm_stage(w2i, w2h, b2v, h1sm[1 - cur], h2sm[cur], h2sm[1 - cur], c2, u);
        __syncthreads();

        // ---- stage 5: fc2 + tanh -> prev (into insm[.][100..104]) + output ----
        {
            int wid = u >> 5, lane = u & 31;
            float (*h2n)[HID] = h2sm[1 - cur];
            for (int p = wid; p < 20; p += 8) {
                int j = p >> 2, r = p & 3;
                float s = 0.0f;
#pragma unroll
                for (int i = 0; i < 8; i++) {
                    int uu = lane + 32 * i;
                    s += fc2_w[j * HID + uu] * h2n[r][uu];
                }
#pragma unroll
                for (int o = 16; o; o >>= 1) s += __shfl_down_sync(0xffffffffu, s, o);
                if (lane == 0) {
                    float v = tanh_f(s + fc2_b[j]);
                    insm[r][ZS + j] = v;
                    out[(size_t)(b0 + r) * (SEQL * FLATD) + (size_t)t * FLATD + j] = v;
                }
            }
        }
        __syncthreads();
        cur ^= 1;
    }
}

// ---------------- launch ------------------------------------------------------
extern "C" void kernel_launch(void* const* d_in, const int* in_sizes, int n_in,
                              void* d_out, int out_size) {
    (void)in_sizes; (void)n_in; (void)out_size;
    const float* z        = (const float*)d_in[0];
    const float* prev_gen = (const float*)d_in[1];
    const float* fc1_w    = (const float*)d_in[2];
    const float* fc1_b    = (const float*)d_in[3];
    const float* w_ih1    = (const float*)d_in[4];
    const float* w_hh1    = (const float*)d_in[5];
    const float* b_ih1    = (const float*)d_in[6];
    const float* b_hh1    = (const float*)d_in[7];
    const float* w_ih2    = (const float*)d_in[8];
    const float* w_hh2    = (const float*)d_in[9];
    const float* b_ih2    = (const float*)d_in[10];
    const float* b_hh2    = (const float*)d_in[11];
    const float* fc2_w    = (const float*)d_in[12];
    const float* fc2_b    = (const float*)d_in[13];
    float* out = (float*)d_out;

    // repack weights (deterministic; ordered before main kernel on same stream)
    const int total = 4 * HID * HID * 4 + 2 * HID * 4 + IN1 * HID;  // 1077504
    repack_kernel<<<(total + 255) / 256, 256>>>(w_ih1, w_hh1, w_ih2, w_hh2,
                                                b_ih1, b_hh1, b_ih2, b_hh2, fc1_w);

    gen_kernel<<<BATCH / 4, HID>>>(z, prev_gen, fc1_b, fc2_w, fc2_b, out);
}

// round 6
// speedup vs baseline: 1.0364x; 1.0364x over previous
#include <cuda_runtime.h>
#include <cuda_bf16.h>

#define SEQL 601
#define BATCH 512
#define ZS 100
#define FLATD 5
#define HID 256
#define IN1 105  // ZS + FLATD

// ---------------- scratch (__device__ globals; no allocation) ----------------
// LSTM weights repacked to bf16: [k][u][gate], each uint = (bf16 w_ih | bf16 w_hh << 16)
__device__ unsigned g_w1[HID * HID * 4];
__device__ unsigned g_w2[HID * HID * 4];
__device__ float g_b1[HID * 4];      // [u][gate] = b_ih + b_hh  (fp32)
__device__ float g_b2[HID * 4];
__device__ float g_fc1t[IN1 * HID];  // [k][n]  (transposed fc1_w, fp32)

// ---------------- weight repack kernel (cheap, runs every launch) ------------
__global__ void repack_kernel(const float* __restrict__ w_ih1,
                              const float* __restrict__ w_hh1,
                              const float* __restrict__ w_ih2,
                              const float* __restrict__ w_hh2,
                              const float* __restrict__ b_ih1,
                              const float* __restrict__ b_hh1,
                              const float* __restrict__ b_ih2,
                              const float* __restrict__ b_hh2,
                              const float* __restrict__ fc1_w) {
    int idx = blockIdx.x * blockDim.x + threadIdx.x;
    const int NP = HID * HID * 4;  // 262144 pairs per LSTM
    if (idx < 2 * NP) {
        int m = idx / NP;
        int e = idx % NP;
        int g = e & 3;
        int u = (e >> 2) & (HID - 1);
        int k = e >> 10;
        const float* wih = m ? w_ih2 : w_ih1;
        const float* whh = m ? w_hh2 : w_hh1;
        unsigned a = (unsigned)__bfloat16_as_ushort(__float2bfloat16(wih[(g * HID + u) * HID + k]));
        unsigned b = (unsigned)__bfloat16_as_ushort(__float2bfloat16(whh[(g * HID + u) * HID + k]));
        unsigned* dst = m ? g_w2 : g_w1;
        dst[e] = a | (b << 16);
    } else {
        int e = idx - 2 * NP;
        if (e < 2 * HID * 4) {  // 2048 bias entries
            int which = e / (HID * 4);
            int r = e % (HID * 4);
            int g = r & 3, u = r >> 2;
            if (which == 0)
                g_b1[r] = b_ih1[g * HID + u] + b_hh1[g * HID + u];
            else
                g_b2[r] = b_ih2[g * HID + u] + b_hh2[g * HID + u];
        } else {
            e -= 2 * HID * 4;
            if (e < IN1 * HID) {
                int n = e % HID, k = e / HID;
                g_fc1t[k * HID + n] = fc1_w[n * IN1 + k];
            }
        }
    }
}

// ---------------- activations (exact saturation at +-inf) --------------------
__device__ __forceinline__ float sigm_f(float x) {
    return __fdividef(1.0f, 1.0f + __expf(-x));
}
__device__ __forceinline__ float tanh_f(float x) {
    float e = __expf(-2.0f * x);
    return __fdividef(2.0f, 1.0f + e) - 1.0f;
}

// ---------------- f32x2 helpers ----------------------------------------------
// bf16 pair (lo=w_ih, hi=w_hh) -> f32x2 (lane0 = w_ih, lane1 = w_hh). Exact.
__device__ __forceinline__ unsigned long long cvtw(unsigned c) {
    unsigned lo = c << 16;
    unsigned hi = c & 0xffff0000u;
    unsigned long long p;
    asm("mov.b64 %0, {%1, %2};" : "=l"(p) : "r"(lo), "r"(hi));
    return p;
}
__device__ __forceinline__ void fma2(unsigned long long& acc, unsigned long long w,
                                     unsigned long long xh) {
    asm("fma.rn.f32x2 %0, %1, %2, %3;" : "=l"(acc) : "l"(w), "l"(xh), "l"(acc));
}
// lane0 + lane1 + bias
__device__ __forceinline__ float redu(unsigned long long a, float b) {
    unsigned lo, hi;
    asm("mov.b64 {%0, %1}, %2;" : "=r"(lo), "=r"(hi) : "l"(a));
    return __uint_as_float(lo) + __uint_as_float(hi) + b;
}

// ---------------- LSTM cell stage (bf16 weights, f32x2 math) -----------------
// w   : [k][u] uint4 = 4 gate-pairs (ih|hh bf16)
// xh  : smem [row][k] float2 = (input_k, hprev_k)   -- broadcast reads
// Computes gates, updates c[], returns new h per row in hres[] (caller stores).
__device__ __forceinline__ void lstm_stage2(const uint4* __restrict__ w,
                                            float4 bv,
                                            const float2 (*__restrict__ xh)[HID],
                                            float* c, float* hres, int u) {
    unsigned long long ai[4] = {0, 0, 0, 0};
    unsigned long long af[4] = {0, 0, 0, 0};
    unsigned long long ag[4] = {0, 0, 0, 0};
    unsigned long long ao[4] = {0, 0, 0, 0};
    const ulonglong2* xr0 = (const ulonglong2*)xh[0];
    const ulonglong2* xr1 = (const ulonglong2*)xh[1];
    const ulonglong2* xr2 = (const ulonglong2*)xh[2];
    const ulonglong2* xr3 = (const ulonglong2*)xh[3];
#pragma unroll 4
    for (int k2 = 0; k2 < HID / 2; k2++) {
        uint4 wA = w[(2 * k2 + 0) * HID + u];
        uint4 wB = w[(2 * k2 + 1) * HID + u];
        ulonglong2 xv0 = xr0[k2];
        ulonglong2 xv1 = xr1[k2];
        ulonglong2 xv2 = xr2[k2];
        ulonglong2 xv3 = xr3[k2];
        unsigned long long wi = cvtw(wA.x);
        unsigned long long wf = cvtw(wA.y);
        unsigned long long wg = cvtw(wA.z);
        unsigned long long wo = cvtw(wA.w);
        fma2(ai[0], wi, xv0.x); fma2(af[0], wf, xv0.x); fma2(ag[0], wg, xv0.x); fma2(ao[0], wo, xv0.x);
        fma2(ai[1], wi, xv1.x); fma2(af[1], wf, xv1.x); fma2(ag[1], wg, xv1.x); fma2(ao[1], wo, xv1.x);
        fma2(ai[2], wi, xv2.x); fma2(af[2], wf, xv2.x); fma2(ag[2], wg, xv2.x); fma2(ao[2], wo, xv2.x);
        fma2(ai[3], wi, xv3.x); fma2(af[3], wf, xv3.x); fma2(ag[3], wg, xv3.x); fma2(ao[3], wo, xv3.x);
        wi = cvtw(wB.x);
        wf = cvtw(wB.y);
        wg = cvtw(wB.z);
        wo = cvtw(wB.w);
        fma2(ai[0], wi, xv0.y); fma2(af[0], wf, xv0.y); fma2(ag[0], wg, xv0.y); fma2(ao[0], wo, xv0.y);
        fma2(ai[1], wi, xv1.y); fma2(af[1], wf, xv1.y); fma2(ag[1], wg, xv1.y); fma2(ao[1], wo, xv1.y);
        fma2(ai[2], wi, xv2.y); fma2(af[2], wf, xv2.y); fma2(ag[2], wg, xv2.y); fma2(ao[2], wo, xv2.y);
        fma2(ai[3], wi, xv3.y); fma2(af[3], wf, xv3.y); fma2(ag[3], wg, xv3.y); fma2(ao[3], wo, xv3.y);
    }
#pragma unroll
    for (int r = 0; r < 4; r++) {
        float iv = sigm_f(redu(ai[r], bv.x));
        float fv = sigm_f(redu(af[r], bv.y));
        float gv = tanh_f(redu(ag[r], bv.z));
        float ov = sigm_f(redu(ao[r], bv.w));
        float cn = fv * c[r] + iv * gv;
        c[r] = cn;
        hres[r] = ov * tanh_f(cn);
    }
}

// ---------------- main persistent kernel: CTA owns 4 batch rows --------------
__global__ void __launch_bounds__(256, 1) gen_kernel(
    const float* __restrict__ z,         // [B][S][ZS]
    const float* __restrict__ prev_gen,  // [B][FLATD]
    const float* __restrict__ fc1_b,     // [HID]
    const float* __restrict__ fc2_w,     // [FLATD][HID]
    const float* __restrict__ fc2_b,     // [FLATD]
    float* __restrict__ out)             // [B][S][FLATD]
{
    __shared__ __align__(16) float insm[4][112];   // [row][k<105]; [100..104] = prev
    __shared__ __align__(16) float2 A1[4][HID];    // (x_t, h1_{t-1})
    __shared__ __align__(16) float2 A2[4][HID];    // (h1_t, h2_{t-1})

    const int u = threadIdx.x;
    const int b0 = blockIdx.x * 4;

#pragma unroll
    for (int r = 0; r < 4; r++) {
        A1[r][u].y = 0.0f;  // h1 prev
        A2[r][u].y = 0.0f;  // h2 prev
    }
    if (u < 20) {
        int r = u / 5, j = u % 5;
        insm[r][ZS + j] = prev_gen[(b0 + r) * FLATD + j];
    }
    float c1[4] = {0.f, 0.f, 0.f, 0.f};
    float c2[4] = {0.f, 0.f, 0.f, 0.f};
    const float fb = fc1_b[u];
    const float4 b1v = ((const float4*)g_b1)[u];
    const float4 b2v = ((const float4*)g_b2)[u];
    const uint4* w1 = (const uint4*)g_w1;
    const uint4* w2 = (const uint4*)g_w2;
    __syncthreads();

    for (int t = 0; t < SEQL; ++t) {
        // ---- stage 1: stage z rows into smem ----
        for (int e = u; e < 4 * ZS; e += 256) {
            int r = e / ZS, k = e % ZS;
            insm[r][k] = z[(size_t)(b0 + r) * (SEQL * ZS) + (size_t)t * ZS + k];
        }
        __syncthreads();

        // ---- stage 2: fc1 + relu -> A1.x ----
        {
            float a0 = fb, a1 = fb, a2 = fb, a3 = fb;
#pragma unroll 5
            for (int k = 0; k < IN1; k++) {
                float w = g_fc1t[k * HID + u];
                a0 += w * insm[0][k];
                a1 += w * insm[1][k];
                a2 += w * insm[2][k];
                a3 += w * insm[3][k];
            }
            A1[0][u].x = fmaxf(a0, 0.0f);
            A1[1][u].x = fmaxf(a1, 0.0f);
            A1[2][u].x = fmaxf(a2, 0.0f);
            A1[3][u].x = fmaxf(a3, 0.0f);
        }
        __syncthreads();

        // ---- stage 3: LSTM1 (reads A1 = (x, h1prev)) ----
        float h1v[4];
        lstm_stage2(w1, b1v, A1, c1, h1v, u);
        __syncthreads();  // all A1 reads complete
#pragma unroll
        for (int r = 0; r < 4; r++) {
            A1[r][u].y = h1v[r];  // h1 for step t+1
            A2[r][u].x = h1v[r];  // h1 input to LSTM2 now
        }
        __syncthreads();

        // ---- stage 4: LSTM2 (reads A2 = (h1, h2prev)) ----
        float h2v[4];
        lstm_stage2(w2, b2v, A2, c2, h2v, u);
        __syncthreads();  // all A2 reads complete
#pragma unroll
        for (int r = 0; r < 4; r++) A2[r][u].y = h2v[r];
        __syncthreads();

        // ---- stage 5: fc2 + tanh -> prev + output ----
        {
            int wid = u >> 5, lane = u & 31;
            for (int p = wid; p < 20; p += 8) {
                int j = p >> 2, r = p & 3;
                float s = 0.0f;
#pragma unroll
                for (int i = 0; i < 8; i++) {
                    int uu = lane + 32 * i;
                    s += fc2_w[j * HID + uu] * A2[r][uu].y;
                }
#pragma unroll
                for (int o = 16; o; o >>= 1) s += __shfl_down_sync(0xffffffffu, s, o);
                if (lane == 0) {
                    float v = tanh_f(s + fc2_b[j]);
                    insm[r][ZS + j] = v;
                    out[(size_t)(b0 + r) * (SEQL * FLATD) + (size_t)t * FLATD + j] = v;
                }
            }
        }
        __syncthreads();
    }
}

// ---------------- launch ------------------------------------------------------
extern "C" void kernel_launch(void* const* d_in, const int* in_sizes, int n_in,
                              void* d_out, int out_size) {
    (void)in_sizes; (void)n_in; (void)out_size;
    const float* z        = (const float*)d_in[0];
    const float* prev_gen = (const float*)d_in[1];
    const float* fc1_w    = (const float*)d_in[2];
    const float* fc1_b    = (const float*)d_in[3];
    const float* w_ih1    = (const float*)d_in[4];
    const float* w_hh1    = (const float*)d_in[5];
    const float* b_ih1    = (const float*)d_in[6];
    const float* b_hh1    = (const float*)d_in[7];
    const float* w_ih2    = (const float*)d_in[8];
    const float* w_hh2    = (const float*)d_in[9];
    const float* b_ih2    = (const float*)d_in[10];
    const float* b_hh2    = (const float*)d_in[11];
    const float* fc2_w    = (const float*)d_in[12];
    const float* fc2_b    = (const float*)d_in[13];
    float* out = (float*)d_out;

    const int total = 2 * HID * HID * 4 + 2 * HID * 4 + IN1 * HID;
    repack_kernel<<<(total + 255) / 256, 256>>>(w_ih1, w_hh1, w_ih2, w_hh2,
                                                b_ih1, b_hh1, b_ih2, b_hh2, fc1_w);

    gen_kernel<<<BATCH / 4, HID>>>(z, prev_gen, fc1_b, fc2_w, fc2_b, out);
}

// round 7
// speedup vs baseline: 1.2689x; 1.2243x over previous
#include <cuda_runtime.h>
#include <cuda_bf16.h>

#define SEQL 601
#define BATCH 512
#define ZS 100
#define FLATD 5
#define HID 256
#define IN1 105  // ZS + FLATD
#define TPB 512

// ---------------- scratch (__device__ globals; no allocation) ----------------
// LSTM weights repacked to bf16: [k][u][gate], each uint = (bf16 w_ih | bf16 w_hh << 16)
__device__ unsigned g_w1[HID * HID * 4];
__device__ unsigned g_w2[HID * HID * 4];
__device__ float g_b1[HID * 4];      // [u][gate] = b_ih + b_hh  (fp32)
__device__ float g_b2[HID * 4];
__device__ float g_fc1t[IN1 * HID];  // [k][n]  (transposed fc1_w, fp32)

// ---------------- weight repack kernel (cheap, runs every launch) ------------
__global__ void repack_kernel(const float* __restrict__ w_ih1,
                              const float* __restrict__ w_hh1,
                              const float* __restrict__ w_ih2,
                              const float* __restrict__ w_hh2,
                              const float* __restrict__ b_ih1,
                              const float* __restrict__ b_hh1,
                              const float* __restrict__ b_ih2,
                              const float* __restrict__ b_hh2,
                              const float* __restrict__ fc1_w) {
    int idx = blockIdx.x * blockDim.x + threadIdx.x;
    const int NP = HID * HID * 4;  // 262144 pairs per LSTM
    if (idx < 2 * NP) {
        int m = idx / NP;
        int e = idx % NP;
        int g = e & 3;
        int u = (e >> 2) & (HID - 1);
        int k = e >> 10;
        const float* wih = m ? w_ih2 : w_ih1;
        const float* whh = m ? w_hh2 : w_hh1;
        unsigned a = (unsigned)__bfloat16_as_ushort(__float2bfloat16(wih[(g * HID + u) * HID + k]));
        unsigned b = (unsigned)__bfloat16_as_ushort(__float2bfloat16(whh[(g * HID + u) * HID + k]));
        unsigned* dst = m ? g_w2 : g_w1;
        dst[e] = a | (b << 16);
    } else {
        int e = idx - 2 * NP;
        if (e < 2 * HID * 4) {
            int which = e / (HID * 4);
            int r = e % (HID * 4);
            int g = r & 3, u = r >> 2;
            if (which == 0)
                g_b1[r] = b_ih1[g * HID + u] + b_hh1[g * HID + u];
            else
                g_b2[r] = b_ih2[g * HID + u] + b_hh2[g * HID + u];
        } else {
            e -= 2 * HID * 4;
            if (e < IN1 * HID) {
                int n = e % HID, k = e / HID;
                g_fc1t[k * HID + n] = fc1_w[n * IN1 + k];
            }
        }
    }
}

// ---------------- activations -------------------------------------------------
__device__ __forceinline__ float sigm_f(float x) {
    return __fdividef(1.0f, 1.0f + __expf(-x));
}
__device__ __forceinline__ float tanh_f(float x) {
    float e = __expf(-2.0f * x);
    return __fdividef(2.0f, 1.0f + e) - 1.0f;
}

// ---------------- f32x2 helpers -----------------------------------------------
__device__ __forceinline__ unsigned long long cvtw(unsigned c) {
    unsigned lo = c << 16;
    unsigned hi = c & 0xffff0000u;
    unsigned long long p;
    asm("mov.b64 %0, {%1, %2};" : "=l"(p) : "r"(lo), "r"(hi));
    return p;
}
__device__ __forceinline__ void fma2(unsigned long long& acc, unsigned long long w,
                                     unsigned long long xh) {
    asm("fma.rn.f32x2 %0, %1, %2, %3;" : "=l"(acc) : "l"(w), "l"(xh), "l"(acc));
}
__device__ __forceinline__ float redu0(unsigned long long a) {
    unsigned lo, hi;
    asm("mov.b64 {%0, %1}, %2;" : "=r"(lo), "=r"(hi) : "l"(a));
    return __uint_as_float(lo) + __uint_as_float(hi);
}

// ---------------- LSTM accumulate over 64 k2-iters (half of K) ----------------
// w  : weight base already offset to this half's first k  ([k][u] uint4)
// x0..x3 : per-row activation pair pointers, offset to this half's first k2
// acc[g*4+r]
__device__ __forceinline__ void lstm_accum(const uint4* __restrict__ w,
                                           const ulonglong2* __restrict__ x0,
                                           const ulonglong2* __restrict__ x1,
                                           const ulonglong2* __restrict__ x2,
                                           const ulonglong2* __restrict__ x3,
                                           int u, unsigned long long* acc) {
#pragma unroll 4
    for (int k2 = 0; k2 < 64; k2++) {
        uint4 wA = w[(2 * k2 + 0) * HID + u];
        uint4 wB = w[(2 * k2 + 1) * HID + u];
        ulonglong2 xv0 = x0[k2];
        ulonglong2 xv1 = x1[k2];
        ulonglong2 xv2 = x2[k2];
        ulonglong2 xv3 = x3[k2];
        unsigned long long wi = cvtw(wA.x);
        unsigned long long wf = cvtw(wA.y);
        unsigned long long wg = cvtw(wA.z);
        unsigned long long wo = cvtw(wA.w);
        fma2(acc[0], wi, xv0.x); fma2(acc[4], wf, xv0.x); fma2(acc[8],  wg, xv0.x); fma2(acc[12], wo, xv0.x);
        fma2(acc[1], wi, xv1.x); fma2(acc[5], wf, xv1.x); fma2(acc[9],  wg, xv1.x); fma2(acc[13], wo, xv1.x);
        fma2(acc[2], wi, xv2.x); fma2(acc[6], wf, xv2.x); fma2(acc[10], wg, xv2.x); fma2(acc[14], wo, xv2.x);
        fma2(acc[3], wi, xv3.x); fma2(acc[7], wf, xv3.x); fma2(acc[11], wg, xv3.x); fma2(acc[15], wo, xv3.x);
        wi = cvtw(wB.x);
        wf = cvtw(wB.y);
        wg = cvtw(wB.z);
        wo = cvtw(wB.w);
        fma2(acc[0], wi, xv0.y); fma2(acc[4], wf, xv0.y); fma2(acc[8],  wg, xv0.y); fma2(acc[12], wo, xv0.y);
        fma2(acc[1], wi, xv1.y); fma2(acc[5], wf, xv1.y); fma2(acc[9],  wg, xv1.y); fma2(acc[13], wo, xv1.y);
        fma2(acc[2], wi, xv2.y); fma2(acc[6], wf, xv2.y); fma2(acc[10], wg, xv2.y); fma2(acc[14], wo, xv2.y);
        fma2(acc[3], wi, xv3.y); fma2(acc[7], wf, xv3.y); fma2(acc[11], wg, xv3.y); fma2(acc[15], wo, xv3.y);
    }
}

// ---------------- main persistent kernel: CTA owns 4 batch rows ---------------
// 512 threads: thread = (u, half). half0: k in [0,128); half1: k in [128,256).
__global__ void __launch_bounds__(TPB, 1) gen_kernel(
    const float* __restrict__ z,         // [B][S][ZS]
    const float* __restrict__ prev_gen,  // [B][FLATD]
    const float* __restrict__ fc1_b,     // [HID]
    const float* __restrict__ fc2_w,     // [FLATD][HID]
    const float* __restrict__ fc2_b,     // [FLATD]
    float* __restrict__ out)             // [B][S][FLATD]
{
    __shared__ __align__(16) float insm[4][112];   // [row][k<105]; [100..104] = prev
    __shared__ __align__(16) float2 A1[4][HID];    // (x_t, h1_{t-1})
    __shared__ __align__(16) float2 A2[4][HID];    // (h1_t, h2_{t-1})
    __shared__ __align__(16) float red[16][HID];   // hi-half partial sums [g*4+r][u]

    const int tid = threadIdx.x;
    const int u = tid & (HID - 1);
    const int half = tid >> 8;
    const int b0 = blockIdx.x * 4;

    if (!half) {
#pragma unroll
        for (int r = 0; r < 4; r++) {
            A1[r][u].y = 0.0f;
            A2[r][u].y = 0.0f;
        }
    }
    if (tid < 20) {
        int r = tid / 5, j = tid % 5;
        insm[r][ZS + j] = prev_gen[(b0 + r) * FLATD + j];
    }
    float c1[4] = {0.f, 0.f, 0.f, 0.f};
    float c2[4] = {0.f, 0.f, 0.f, 0.f};
    const float fb = fc1_b[u];
    const float4 b1v = ((const float4*)g_b1)[u];
    const float4 b2v = ((const float4*)g_b2)[u];
    // this half's weight/activation base offsets
    const uint4* w1h = (const uint4*)g_w1 + (size_t)half * 128 * HID;
    const uint4* w2h = (const uint4*)g_w2 + (size_t)half * 128 * HID;
    const int xoff = half * 64;  // in ulonglong2 units (2 k per element)
    __syncthreads();

    for (int t = 0; t < SEQL; ++t) {
        // ---- stage 1: stage z rows into smem ----
        {
            int e = tid;
            if (e < 4 * ZS) {
                int r = e / ZS, k = e % ZS;
                insm[r][k] = z[(size_t)(b0 + r) * (SEQL * ZS) + (size_t)t * ZS + k];
            }
        }
        __syncthreads();  // B1: insm (z + prev) ready

        // ---- stage 2: fc1 + relu -> A1.x  (half0: rows 0,1; half1: rows 2,3) ----
        {
            int r0 = half * 2, r1 = r0 + 1;
            float a0 = fb, a1 = fb;
#pragma unroll 5
            for (int k = 0; k < IN1; k++) {
                float w = g_fc1t[k * HID + u];
                a0 += w * insm[r0][k];
                a1 += w * insm[r1][k];
            }
            A1[r0][u].x = fmaxf(a0, 0.0f);
            A1[r1][u].x = fmaxf(a1, 0.0f);
        }
        __syncthreads();  // B2: A1 = (x, h1prev) ready

        // ---- stage 3: LSTM1 ----
        {
            unsigned long long acc[16];
#pragma unroll
            for (int j = 0; j < 16; j++) acc[j] = 0ull;
            lstm_accum(w1h, (const ulonglong2*)A1[0] + xoff, (const ulonglong2*)A1[1] + xoff,
                       (const ulonglong2*)A1[2] + xoff, (const ulonglong2*)A1[3] + xoff, u, acc);
            if (half) {
#pragma unroll
                for (int j = 0; j < 16; j++) red[j][u] = redu0(acc[j]);
            }
            __syncthreads();  // B3: partials ready (also: all A1 reads done)
            if (!half) {
#pragma unroll
                for (int r = 0; r < 4; r++) {
                    float iv = sigm_f(redu0(acc[0 + r]) + red[0 + r][u] + b1v.x);
                    float fv = sigm_f(redu0(acc[4 + r]) + red[4 + r][u] + b1v.y);
                    float gv = tanh_f(redu0(acc[8 + r]) + red[8 + r][u] + b1v.z);
                    float ov = sigm_f(redu0(acc[12 + r]) + red[12 + r][u] + b1v.w);
                    float cn = fv * c1[r] + iv * gv;
                    c1[r] = cn;
                    float hv = ov * tanh_f(cn);
                    A1[r][u].y = hv;  // h1 for step t+1
                    A2[r][u].x = hv;  // h1 input to LSTM2 now
                }
            }
        }
        __syncthreads();  // B4: A2 = (h1, h2prev) ready

        // ---- stage 4: LSTM2 ----
        {
            unsigned long long acc[16];
#pragma unroll
            for (int j = 0; j < 16; j++) acc[j] = 0ull;
            lstm_accum(w2h, (const ulonglong2*)A2[0] + xoff, (const ulonglong2*)A2[1] + xoff,
                       (const ulonglong2*)A2[2] + xoff, (const ulonglong2*)A2[3] + xoff, u, acc);
            if (half) {
#pragma unroll
                for (int j = 0; j < 16; j++) red[j][u] = redu0(acc[j]);
            }
            __syncthreads();  // B5
            if (!half) {
#pragma unroll
                for (int r = 0; r < 4; r++) {
                    float iv = sigm_f(redu0(acc[0 + r]) + red[0 + r][u] + b2v.x);
                    float fv = sigm_f(redu0(acc[4 + r]) + red[4 + r][u] + b2v.y);
                    float gv = tanh_f(redu0(acc[8 + r]) + red[8 + r][u] + b2v.z);
                    float ov = sigm_f(redu0(acc[12 + r]) + red[12 + r][u] + b2v.w);
                    float cn = fv * c2[r] + iv * gv;
                    c2[r] = cn;
                    A2[r][u].y = ov * tanh_f(cn);
                }
            }
        }
        __syncthreads();  // B6: h2 ready

        // ---- stage 5: fc2 + tanh -> prev + output (16 warps) ----
        {
            int wid = tid >> 5, lane = tid & 31;
            for (int p = wid; p < 20; p += 16) {
                int j = p >> 2, r = p & 3;
                float s = 0.0f;
#pragma unroll
                for (int i = 0; i < 8; i++) {
                    int uu = lane + 32 * i;
                    s += fc2_w[j * HID + uu] * A2[r][uu].y;
                }
#pragma unroll
                for (int o = 16; o; o >>= 1) s += __shfl_down_sync(0xffffffffu, s, o);
                if (lane == 0) {
                    float v = tanh_f(s + fc2_b[j]);
                    insm[r][ZS + j] = v;
                    out[(size_t)(b0 + r) * (SEQL * FLATD) + (size_t)t * FLATD + j] = v;
                }
            }
        }
        // no barrier needed here: stage1 writes disjoint insm cells; B1 orders
        // both stage5's insm writes and stage1's z writes before fc1 reads.
    }
}

// ---------------- launch ------------------------------------------------------
extern "C" void kernel_launch(void* const* d_in, const int* in_sizes, int n_in,
                              void* d_out, int out_size) {
    (void)in_sizes; (void)n_in; (void)out_size;
    const float* z        = (const float*)d_in[0];
    const float* prev_gen = (const float*)d_in[1];
    const float* fc1_w    = (const float*)d_in[2];
    const float* fc1_b    = (const float*)d_in[3];
    const float* w_ih1    = (const float*)d_in[4];
    const float* w_hh1    = (const float*)d_in[5];
    const float* b_ih1    = (const float*)d_in[6];
    const float* b_hh1    = (const float*)d_in[7];
    const float* w_ih2    = (const float*)d_in[8];
    const float* w_hh2    = (const float*)d_in[9];
    const float* b_ih2    = (const float*)d_in[10];
    const float* b_hh2    = (const float*)d_in[11];
    const float* fc2_w    = (const float*)d_in[12];
    const float* fc2_b    = (const float*)d_in[13];
    float* out = (float*)d_out;

    const int total = 2 * HID * HID * 4 + 2 * HID * 4 + IN1 * HID;
    repack_kernel<<<(total + 255) / 256, 256>>>(w_ih1, w_hh1, w_ih2, w_hh2,
                                                b_ih1, b_hh1, b_ih2, b_hh2, fc1_w);

    gen_kernel<<<BATCH / 4, TPB>>>(z, prev_gen, fc1_b, fc2_w, fc2_b, out);
}